// round 1
// baseline (speedup 1.0000x reference)
#include <cuda_runtime.h>
#include <cstddef>

#define NN   128
#define PL   16384      // 128*128
#define VOL  2097152    // 128^3

// Scratch buffers (static device allocations are the sanctioned workaround).
__device__ float g_A[8 * VOL];
__device__ float g_B[8 * VOL];
__device__ float g_C[8 * VOL];
__device__ float g_W[27 * VOL];
__device__ float g_f1[VOL];
__device__ float g_f2[VOL];

// ---------------------------------------------------------------------------
// Generic 3x3x3 conv, C_in = 8 fixed, C_out = CO (1/8/27).
// Each thread computes 2 voxels (w0, w0+1). Weights staged in shared,
// co-major (padded to 4) so the inner loop vectorizes to LDS.128.
// NORM: fuse per-voxel L1 normalization over the CO channels (eps 1e-12).
// ---------------------------------------------------------------------------
template<int CO, bool RELU, bool NORM, bool HB>
__global__ void __launch_bounds__(256) conv_k(
    const float* __restrict__ in, const float* __restrict__ wgt,
    const float* __restrict__ bias, float* __restrict__ out)
{
    constexpr int COP = (CO + 3) & ~3;
    __shared__ __align__(16) float sw[8 * 27 * COP];

    for (int i = threadIdx.x; i < 8 * 27 * COP; i += 256) {
        int co   = i % COP;
        int rest = i / COP;          // ci*27 + tap
        int ci   = rest / 27;
        int tap  = rest % 27;
        sw[i] = (co < CO) ? wgt[(co * 8 + ci) * 27 + tap] : 0.f;
    }
    __syncthreads();

    int t  = blockIdx.x * 256 + threadIdx.x;   // [0, VOL/2)
    int w0 = (t & 63) << 1;
    int h  = (t >> 6) & 127;
    int d  = t >> 13;
    long pos = ((long)d << 14) + (h << 7) + w0;

    float acc0[COP], acc1[COP];
#pragma unroll
    for (int co = 0; co < COP; co++) {
        float b = 0.f;
        if (HB && co < CO) b = bias[co];
        acc0[co] = b; acc1[co] = b;
    }

    bool wl = (w0 > 0);
    bool wr = (w0 < 126);

#pragma unroll 1
    for (int ci = 0; ci < 8; ci++) {
        const float* cb  = in + (long)ci * VOL + pos;
        const float* swc = sw + ci * 27 * COP;
#pragma unroll
        for (int dz = -1; dz <= 1; dz++) {
            bool zok = (unsigned)(d + dz) < 128u;
#pragma unroll
            for (int dy = -1; dy <= 1; dy++) {
                bool ok = zok && ((unsigned)(h + dy) < 128u);
                const float* r = cb + dz * PL + dy * NN;
                float v0 = (ok && wl) ? r[-1] : 0.f;
                float v1 = ok ? r[0] : 0.f;
                float v2 = ok ? r[1] : 0.f;
                float v3 = (ok && wr) ? r[2] : 0.f;
                const float* sp = swc + ((dz + 1) * 9 + (dy + 1) * 3) * COP;
#pragma unroll
                for (int co = 0; co < COP; co++) {
                    float wv = sp[co];                 // dx = -1
                    acc0[co] += v0 * wv;
                    acc1[co] += v1 * wv;
                }
#pragma unroll
                for (int co = 0; co < COP; co++) {
                    float wv = sp[COP + co];           // dx = 0
                    acc0[co] += v1 * wv;
                    acc1[co] += v2 * wv;
                }
#pragma unroll
                for (int co = 0; co < COP; co++) {
                    float wv = sp[2 * COP + co];       // dx = +1
                    acc0[co] += v2 * wv;
                    acc1[co] += v3 * wv;
                }
            }
        }
    }

    if (NORM) {
        float s0 = 0.f, s1 = 0.f;
#pragma unroll
        for (int co = 0; co < CO; co++) { s0 += fabsf(acc0[co]); s1 += fabsf(acc1[co]); }
        float i0 = 1.f / fmaxf(s0, 1e-12f);
        float i1 = 1.f / fmaxf(s1, 1e-12f);
#pragma unroll
        for (int co = 0; co < CO; co++) {
            float2 st; st.x = acc0[co] * i0; st.y = acc1[co] * i1;
            *reinterpret_cast<float2*>(out + (long)co * VOL + pos) = st;
        }
    } else {
#pragma unroll
        for (int co = 0; co < CO; co++) {
            float a = acc0[co], b = acc1[co];
            if (RELU) { a = fmaxf(a, 0.f); b = fmaxf(b, 0.f); }
            float2 st; st.x = a; st.y = b;
            *reinterpret_cast<float2*>(out + (long)co * VOL + pos) = st;
        }
    }
}

// ---------------------------------------------------------------------------
// Adaptive conv: out[c][v] = sum_{tap} in[c][v + off(tap)] * w[tap][v]
// Weights (27 planes) are read at the OUTPUT voxel. 2 voxels per thread.
// ---------------------------------------------------------------------------
template<int C>
__global__ void __launch_bounds__(256) adapt_k(
    const float* __restrict__ in, const float* __restrict__ wt,
    float* __restrict__ out)
{
    int t  = blockIdx.x * 256 + threadIdx.x;
    int w0 = (t & 63) << 1;
    int h  = (t >> 6) & 127;
    int d  = t >> 13;
    long pos = ((long)d << 14) + (h << 7) + w0;

    float acc0[C], acc1[C];
#pragma unroll
    for (int c = 0; c < C; c++) { acc0[c] = 0.f; acc1[c] = 0.f; }

    bool wl = (w0 > 0);
    bool wr = (w0 < 126);

#pragma unroll
    for (int dz = -1; dz <= 1; dz++) {
        bool zok = (unsigned)(d + dz) < 128u;
#pragma unroll
        for (int dy = -1; dy <= 1; dy++) {
            bool ok = zok && ((unsigned)(h + dy) < 128u);
            int tap = (dz + 1) * 9 + (dy + 1) * 3;
            float2 wa = *reinterpret_cast<const float2*>(wt + (long)tap * VOL + pos);
            float2 wb = *reinterpret_cast<const float2*>(wt + (long)(tap + 1) * VOL + pos);
            float2 wc = *reinterpret_cast<const float2*>(wt + (long)(tap + 2) * VOL + pos);
            long off = (long)dz * PL + dy * NN;
#pragma unroll
            for (int c = 0; c < C; c++) {
                const float* r = in + (long)c * VOL + pos + off;
                float v0 = (ok && wl) ? r[-1] : 0.f;
                float v1 = ok ? r[0] : 0.f;
                float v2 = ok ? r[1] : 0.f;
                float v3 = (ok && wr) ? r[2] : 0.f;
                acc0[c] += v0 * wa.x + v1 * wb.x + v2 * wc.x;
                acc1[c] += v1 * wa.y + v2 * wb.y + v3 * wc.y;
            }
        }
    }
#pragma unroll
    for (int c = 0; c < C; c++) {
        float2 st; st.x = acc0[c]; st.y = acc1[c];
        *reinterpret_cast<float2*>(out + (long)c * VOL + pos) = st;
    }
}

extern "C" void kernel_launch(void* const* d_in, const int* in_sizes, int n_in,
                              void* d_out, int out_size)
{
    const float* x    = (const float*)d_in[0];
    const float* a1w1 = (const float*)d_in[1];
    const float* a1b1 = (const float*)d_in[2];
    const float* a1w2 = (const float*)d_in[3];
    const float* a2w1 = (const float*)d_in[4];
    const float* a2b1 = (const float*)d_in[5];
    const float* a2w2 = (const float*)d_in[6];
    const float* a3w1 = (const float*)d_in[7];
    const float* a3b1 = (const float*)d_in[8];
    const float* a3w2 = (const float*)d_in[9];
    const float* midw = (const float*)d_in[10];
    const float* midb = (const float*)d_in[11];
    const float* outw = (const float*)d_in[12];
    const float* outb = (const float*)d_in[13];
    float* y = (float*)d_out;

    float *A, *B, *C, *W, *f1, *f2;
    cudaGetSymbolAddress((void**)&A,  g_A);
    cudaGetSymbolAddress((void**)&B,  g_B);
    cudaGetSymbolAddress((void**)&C,  g_C);
    cudaGetSymbolAddress((void**)&W,  g_W);
    cudaGetSymbolAddress((void**)&f1, g_f1);
    cudaGetSymbolAddress((void**)&f2, g_f2);

    dim3 gr(VOL / 512);   // 4096 blocks * 256 threads * 2 voxels/thread
    dim3 bl(256);

    // ---- block 1 (weights from x) ----
    conv_k<8,  true,  false, true ><<<gr, bl>>>(x, a1w1, a1b1, A);
    conv_k<27, false, true,  false><<<gr, bl>>>(A, a1w2, nullptr, W);
    adapt_k<8><<<gr, bl>>>(x, W, A);
    adapt_k<8><<<gr, bl>>>(A, W, B);
    adapt_k<8><<<gr, bl>>>(B, W, A);              // block1 out -> A

    // ---- mid conv ----
    conv_k<8,  false, false, true ><<<gr, bl>>>(A, midw, midb, B);   // mid -> B

    // ---- block 2 (weights from mid) ----
    conv_k<8,  true,  false, true ><<<gr, bl>>>(B, a2w1, a2b1, A);
    conv_k<27, false, true,  false><<<gr, bl>>>(A, a2w2, nullptr, W);
    adapt_k<8><<<gr, bl>>>(B, W, A);
    adapt_k<8><<<gr, bl>>>(A, W, C);
    adapt_k<8><<<gr, bl>>>(C, W, A);              // block2 out (mid2) -> A

    // ---- out conv (8 -> 1) ----
    conv_k<1,  false, false, true ><<<gr, bl>>>(A, outw, outb, f1);

    // ---- block 3 (weights from mid2 = A, applied to 1-channel final) ----
    conv_k<8,  true,  false, true ><<<gr, bl>>>(A, a3w1, a3b1, B);
    conv_k<27, false, true,  false><<<gr, bl>>>(B, a3w2, nullptr, W);
    adapt_k<1><<<gr, bl>>>(f1, W, f2);
    adapt_k<1><<<gr, bl>>>(f2, W, f1);
    adapt_k<1><<<gr, bl>>>(f1, W, y);
}

// round 2
// speedup vs baseline: 1.0213x; 1.0213x over previous
#include <cuda_runtime.h>
#include <cstddef>

#define NN   128
#define PL   16384      // 128*128
#define VOL  2097152    // 128^3

typedef unsigned long long ull;

__device__ float g_A[8 * VOL];
__device__ float g_B[8 * VOL];
__device__ float g_C[8 * VOL];
__device__ float g_W[27 * VOL];
__device__ float g_f1[VOL];
__device__ float g_f2[VOL];

// ---- packed f32x2 helpers -------------------------------------------------
__device__ __forceinline__ ull f2pk(float lo, float hi) {
    ull r; asm("mov.b64 %0, {%1, %2};" : "=l"(r) : "f"(lo), "f"(hi)); return r;
}
__device__ __forceinline__ float2 f2un(ull v) {
    float2 r; asm("mov.b64 {%0, %1}, %2;" : "=f"(r.x), "=f"(r.y) : "l"(v)); return r;
}
__device__ __forceinline__ ull ffma2(ull a, ull b, ull c) {
    ull d; asm("fma.rn.f32x2 %0, %1, %2, %3;" : "=l"(d) : "l"(a), "l"(b), "l"(c)); return d;
}

// ---------------------------------------------------------------------------
// 3x3x3 conv, C_in = 8, C_out = CO. 2 voxels per thread (w0, w0+1).
// Accumulators packed over OUTPUT-CHANNEL PAIRS (f32x2): weight pairs come
// directly from shared as 64-bit loads (co-major layout), input value is
// duplicated {v,v} once per tap row. FFMA2 halves FMA-pipe instruction count.
// ---------------------------------------------------------------------------
template<int CO, bool RELU, bool NORM, bool HB>
__global__ void __launch_bounds__(256) conv_k(
    const float* __restrict__ in, const float* __restrict__ wgt,
    const float* __restrict__ bias, float* __restrict__ out)
{
    constexpr int COP = (CO + 3) & ~3;   // 4, 8, 28
    constexpr int CP  = COP / 2;
    __shared__ __align__(16) float sw[8 * 27 * COP];

    for (int i = threadIdx.x; i < 8 * 27 * COP; i += 256) {
        int co   = i % COP;
        int rest = i / COP;          // ci*27 + tap
        int ci   = rest / 27;
        int tap  = rest % 27;
        sw[i] = (co < CO) ? wgt[(co * 8 + ci) * 27 + tap] : 0.f;
    }
    __syncthreads();

    int t  = blockIdx.x * 256 + threadIdx.x;   // [0, VOL/2)
    int w0 = (t & 63) << 1;
    int h  = (t >> 6) & 127;
    int d  = t >> 13;
    long pos = ((long)d << 14) + (h << 7) + w0;

    ull acc0[CP], acc1[CP];
#pragma unroll
    for (int p = 0; p < CP; p++) {
        float blo = 0.f, bhi = 0.f;
        if (HB) {
            if (2 * p     < CO) blo = bias[2 * p];
            if (2 * p + 1 < CO) bhi = bias[2 * p + 1];
        }
        ull b = f2pk(blo, bhi);
        acc0[p] = b; acc1[p] = b;
    }

    bool wl = (w0 > 0);
    bool wr = (w0 < 126);

#pragma unroll 1
    for (int ci = 0; ci < 8; ci++) {
        const float* cb  = in + (long)ci * VOL + pos;
        const float* swc = sw + ci * 27 * COP;
#pragma unroll
        for (int dz = -1; dz <= 1; dz++) {
            bool zok = (unsigned)(d + dz) < 128u;
#pragma unroll
            for (int dy = -1; dy <= 1; dy++) {
                bool ok = zok && ((unsigned)(h + dy) < 128u);
                const float* r = cb + dz * PL + dy * NN;
                float v0 = (ok && wl) ? r[-1] : 0.f;
                float v1 = ok ? r[0] : 0.f;
                float v2 = ok ? r[1] : 0.f;
                float v3 = (ok && wr) ? r[2] : 0.f;
                ull vv0 = f2pk(v0, v0);
                ull vv1 = f2pk(v1, v1);
                ull vv2 = f2pk(v2, v2);
                ull vv3 = f2pk(v3, v3);
                const float* sp = swc + ((dz + 1) * 9 + (dy + 1) * 3) * COP;
#pragma unroll
                for (int p = 0; p < CP; p++) {
                    ull wA = *reinterpret_cast<const ull*>(sp + 2 * p);             // dx=-1
                    ull wB = *reinterpret_cast<const ull*>(sp + COP + 2 * p);       // dx= 0
                    ull wC = *reinterpret_cast<const ull*>(sp + 2 * COP + 2 * p);   // dx=+1
                    acc0[p] = ffma2(vv0, wA, acc0[p]);
                    acc1[p] = ffma2(vv1, wA, acc1[p]);
                    acc0[p] = ffma2(vv1, wB, acc0[p]);
                    acc1[p] = ffma2(vv2, wB, acc1[p]);
                    acc0[p] = ffma2(vv2, wC, acc0[p]);
                    acc1[p] = ffma2(vv3, wC, acc1[p]);
                }
            }
        }
    }

    if (NORM) {
        // padded channels have zero weights + zero bias -> contribute 0 to |.| sum
        float s0 = 0.f, s1 = 0.f;
#pragma unroll
        for (int p = 0; p < CP; p++) {
            float2 u0 = f2un(acc0[p]), u1 = f2un(acc1[p]);
            s0 += fabsf(u0.x) + fabsf(u0.y);
            s1 += fabsf(u1.x) + fabsf(u1.y);
        }
        float i0 = 1.f / fmaxf(s0, 1e-12f);
        float i1 = 1.f / fmaxf(s1, 1e-12f);
#pragma unroll
        for (int p = 0; p < CP; p++) {
            float2 u0 = f2un(acc0[p]), u1 = f2un(acc1[p]);
            if (2 * p < CO) {
                float2 st; st.x = u0.x * i0; st.y = u1.x * i1;
                *reinterpret_cast<float2*>(out + (long)(2 * p) * VOL + pos) = st;
            }
            if (2 * p + 1 < CO) {
                float2 st; st.x = u0.y * i0; st.y = u1.y * i1;
                *reinterpret_cast<float2*>(out + (long)(2 * p + 1) * VOL + pos) = st;
            }
        }
    } else {
#pragma unroll
        for (int p = 0; p < CP; p++) {
            float2 u0 = f2un(acc0[p]), u1 = f2un(acc1[p]);
            if (RELU) {
                u0.x = fmaxf(u0.x, 0.f); u0.y = fmaxf(u0.y, 0.f);
                u1.x = fmaxf(u1.x, 0.f); u1.y = fmaxf(u1.y, 0.f);
            }
            if (2 * p < CO) {
                float2 st; st.x = u0.x; st.y = u1.x;
                *reinterpret_cast<float2*>(out + (long)(2 * p) * VOL + pos) = st;
            }
            if (2 * p + 1 < CO) {
                float2 st; st.x = u0.y; st.y = u1.y;
                *reinterpret_cast<float2*>(out + (long)(2 * p + 1) * VOL + pos) = st;
            }
        }
    }
}

// ---------------------------------------------------------------------------
// Adaptive conv: out[c][v] = sum_tap in[c][v + off(tap)] * w[tap][v]
// 4 voxels per thread. Weight pairs load pre-packed as ulonglong2 (16B).
// Center values via one float4 + 2 predicated edge scalars.
// Accumulate as two f32x2 pairs: (v0,v1) and (v2,v3).
// ---------------------------------------------------------------------------
template<int C>
__global__ void __launch_bounds__(256) adapt_k(
    const float* __restrict__ in, const float* __restrict__ wt,
    float* __restrict__ out)
{
    int t  = blockIdx.x * 256 + threadIdx.x;   // [0, VOL/4)
    int w0 = (t & 31) << 2;
    int h  = (t >> 5) & 127;
    int d  = t >> 12;
    long pos = ((long)d << 14) + (h << 7) + w0;

    ull accA[C], accB[C];
#pragma unroll
    for (int c = 0; c < C; c++) { accA[c] = 0ull; accB[c] = 0ull; }

    bool wl = (w0 > 0);
    bool wr = (w0 < 124);

#pragma unroll
    for (int dz = -1; dz <= 1; dz++) {
        bool zok = (unsigned)(d + dz) < 128u;
#pragma unroll
        for (int dy = -1; dy <= 1; dy++) {
            bool ok = zok && ((unsigned)(h + dy) < 128u);
            int tap = (dz + 1) * 9 + (dy + 1) * 3;
            const float* wp = wt + (long)tap * VOL + pos;
            ulonglong2 q0 = *reinterpret_cast<const ulonglong2*>(wp);            // dx=-1
            ulonglong2 q1 = *reinterpret_cast<const ulonglong2*>(wp + VOL);      // dx= 0
            ulonglong2 q2 = *reinterpret_cast<const ulonglong2*>(wp + 2 * VOL);  // dx=+1
            long off = (long)dz * PL + dy * NN;
#pragma unroll
            for (int c = 0; c < C; c++) {
                const float* r = in + (long)c * VOL + pos + off;
                float4 cv;
                if (ok) cv = *reinterpret_cast<const float4*>(r);
                else    { cv.x = 0.f; cv.y = 0.f; cv.z = 0.f; cv.w = 0.f; }
                float vL = (ok && wl) ? r[-1] : 0.f;
                float vR = (ok && wr) ? r[4]  : 0.f;
                ull pm1 = f2pk(vL, cv.x);       // dx=-1, voxels (0,1)
                ull pmid = f2pk(cv.y, cv.z);    // dx=-1 vox(2,3) AND dx=+1 vox(0,1)
                ull p01 = f2pk(cv.x, cv.y);     // dx=0,  voxels (0,1)
                ull p23 = f2pk(cv.z, cv.w);     // dx=0,  voxels (2,3)
                ull pp2 = f2pk(cv.w, vR);       // dx=+1, voxels (2,3)
                accA[c] = ffma2(pm1,  q0.x, accA[c]);
                accB[c] = ffma2(pmid, q0.y, accB[c]);
                accA[c] = ffma2(p01,  q1.x, accA[c]);
                accB[c] = ffma2(p23,  q1.y, accB[c]);
                accA[c] = ffma2(pmid, q2.x, accA[c]);
                accB[c] = ffma2(pp2,  q2.y, accB[c]);
            }
        }
    }
#pragma unroll
    for (int c = 0; c < C; c++) {
        float2 a = f2un(accA[c]);
        float2 b = f2un(accB[c]);
        float4 st; st.x = a.x; st.y = a.y; st.z = b.x; st.w = b.y;
        *reinterpret_cast<float4*>(out + (long)c * VOL + pos) = st;
    }
}

extern "C" void kernel_launch(void* const* d_in, const int* in_sizes, int n_in,
                              void* d_out, int out_size)
{
    const float* x    = (const float*)d_in[0];
    const float* a1w1 = (const float*)d_in[1];
    const float* a1b1 = (const float*)d_in[2];
    const float* a1w2 = (const float*)d_in[3];
    const float* a2w1 = (const float*)d_in[4];
    const float* a2b1 = (const float*)d_in[5];
    const float* a2w2 = (const float*)d_in[6];
    const float* a3w1 = (const float*)d_in[7];
    const float* a3b1 = (const float*)d_in[8];
    const float* a3w2 = (const float*)d_in[9];
    const float* midw = (const float*)d_in[10];
    const float* midb = (const float*)d_in[11];
    const float* outw = (const float*)d_in[12];
    const float* outb = (const float*)d_in[13];
    float* y = (float*)d_out;

    float *A, *B, *C, *W, *f1, *f2;
    cudaGetSymbolAddress((void**)&A,  g_A);
    cudaGetSymbolAddress((void**)&B,  g_B);
    cudaGetSymbolAddress((void**)&C,  g_C);
    cudaGetSymbolAddress((void**)&W,  g_W);
    cudaGetSymbolAddress((void**)&f1, g_f1);
    cudaGetSymbolAddress((void**)&f2, g_f2);

    dim3 gc(VOL / 512);    // conv: 2 voxels/thread
    dim3 ga(VOL / 1024);   // adapt: 4 voxels/thread
    dim3 bl(256);

    // ---- block 1 (weights from x) ----
    conv_k<8,  true,  false, true ><<<gc, bl>>>(x, a1w1, a1b1, A);
    conv_k<27, false, true,  false><<<gc, bl>>>(A, a1w2, nullptr, W);
    adapt_k<8><<<ga, bl>>>(x, W, A);
    adapt_k<8><<<ga, bl>>>(A, W, B);
    adapt_k<8><<<ga, bl>>>(B, W, A);              // block1 out -> A

    // ---- mid conv ----
    conv_k<8,  false, false, true ><<<gc, bl>>>(A, midw, midb, B);   // mid -> B

    // ---- block 2 (weights from mid) ----
    conv_k<8,  true,  false, true ><<<gc, bl>>>(B, a2w1, a2b1, A);
    conv_k<27, false, true,  false><<<gc, bl>>>(A, a2w2, nullptr, W);
    adapt_k<8><<<ga, bl>>>(B, W, A);
    adapt_k<8><<<ga, bl>>>(A, W, C);
    adapt_k<8><<<ga, bl>>>(C, W, A);              // block2 out (mid2) -> A

    // ---- out conv (8 -> 1) ----
    conv_k<1,  false, false, true ><<<gc, bl>>>(A, outw, outb, f1);

    // ---- block 3 (weights from mid2 = A, applied to 1-channel final) ----
    conv_k<8,  true,  false, true ><<<gc, bl>>>(A, a3w1, a3b1, B);
    conv_k<27, false, true,  false><<<gc, bl>>>(B, a3w2, nullptr, W);
    adapt_k<1><<<ga, bl>>>(f1, W, f2);
    adapt_k<1><<<ga, bl>>>(f2, W, f1);
    adapt_k<1><<<ga, bl>>>(f1, W, y);
}

// round 3
// speedup vs baseline: 1.1129x; 1.0897x over previous
#include <cuda_runtime.h>
#include <cstddef>

#define NN   128
#define PL   16384      // 128*128
#define VOL  2097152    // 128^3

typedef unsigned long long ull;

__device__ float g_A[8 * VOL];
__device__ float g_B[8 * VOL];
__device__ float g_C[8 * VOL];
__device__ float g_W[27 * VOL];
__device__ float g_f1[VOL];
__device__ float g_f2[VOL];

// ---- packed f32x2 helpers -------------------------------------------------
__device__ __forceinline__ ull f2pk(float lo, float hi) {
    ull r; asm("mov.b64 %0, {%1, %2};" : "=l"(r) : "f"(lo), "f"(hi)); return r;
}
__device__ __forceinline__ float2 f2un(ull v) {
    float2 r; asm("mov.b64 {%0, %1}, %2;" : "=f"(r.x), "=f"(r.y) : "l"(v)); return r;
}
__device__ __forceinline__ ull ffma2(ull a, ull b, ull c) {
    ull d; asm("fma.rn.f32x2 %0, %1, %2, %3;" : "=l"(d) : "l"(a), "l"(b), "l"(c)); return d;
}

// ---------------------------------------------------------------------------
// 3x3x3 conv, C_in=8, C_out=CO. 4 voxels per thread along w.
// Accumulators packed over output-channel pairs (f32x2); weights staged in
// shared co-major and read as LDS.128 quads (2 co-pairs per load) so the
// weight-load instruction count is 1/8 of the FFMA2 count.
// ---------------------------------------------------------------------------
template<int CO, bool RELU, bool NORM, bool HB>
__global__ void __launch_bounds__(128) conv_k(
    const float* __restrict__ in, const float* __restrict__ wgt,
    const float* __restrict__ bias, float* __restrict__ out)
{
    constexpr int COP = (CO + 1) & ~1;   // 2, 8, 28
    constexpr int CP  = COP / 2;
    __shared__ __align__(16) float sw[8 * 27 * COP];

    for (int i = threadIdx.x; i < 8 * 27 * COP; i += 128) {
        int co   = i % COP;
        int rest = i / COP;          // ci*27 + tap
        int ci   = rest / 27;
        int tap  = rest % 27;
        sw[i] = (co < CO) ? wgt[(co * 8 + ci) * 27 + tap] : 0.f;
    }
    __syncthreads();

    int t  = blockIdx.x * 128 + threadIdx.x;   // [0, VOL/4)
    int w0 = (t & 31) << 2;
    int h  = (t >> 5) & 127;
    int d  = t >> 12;
    int pos = (d << 14) + (h << 7) + w0;

    ull acc[4][CP];
#pragma unroll
    for (int p = 0; p < CP; p++) {
        float blo = 0.f, bhi = 0.f;
        if (HB) {
            if (2 * p     < CO) blo = bias[2 * p];
            if (2 * p + 1 < CO) bhi = bias[2 * p + 1];
        }
        ull b = f2pk(blo, bhi);
#pragma unroll
        for (int v = 0; v < 4; v++) acc[v][p] = b;
    }

    bool wl = (w0 > 0);
    bool wr = (w0 < 124);

#pragma unroll 1
    for (int ci = 0; ci < 8; ci++) {
        const float* cb  = in + ci * VOL + pos;
        const float* swc = sw + ci * 27 * COP;
#pragma unroll
        for (int dz = -1; dz <= 1; dz++) {
            bool zok = (unsigned)(d + dz) < 128u;
#pragma unroll
            for (int dy = -1; dy <= 1; dy++) {
                bool ok = zok && ((unsigned)(h + dy) < 128u);
                const float* r = cb + dz * PL + dy * NN;
                float4 cv;
                if (ok) cv = *reinterpret_cast<const float4*>(r);
                else    { cv.x = 0.f; cv.y = 0.f; cv.z = 0.f; cv.w = 0.f; }
                float vL = (ok && wl) ? r[-1] : 0.f;
                float vR = (ok && wr) ? r[4]  : 0.f;
                // duplicated {v,v} operands, shared across all channel pairs
                ull uL = f2pk(vL,   vL);
                ull uX = f2pk(cv.x, cv.x);
                ull uY = f2pk(cv.y, cv.y);
                ull uZ = f2pk(cv.z, cv.z);
                ull uW = f2pk(cv.w, cv.w);
                ull uR = f2pk(vR,   vR);
                const float* sp = swc + ((dz + 1) * 9 + (dy + 1) * 3) * COP;
                if constexpr (CP % 2 == 0) {
#pragma unroll
                    for (int pp = 0; pp < CP; pp += 2) {
                        ulonglong2 wA = *reinterpret_cast<const ulonglong2*>(sp + 2 * pp);             // dx=-1
                        ulonglong2 wB = *reinterpret_cast<const ulonglong2*>(sp + COP + 2 * pp);       // dx= 0
                        ulonglong2 wC = *reinterpret_cast<const ulonglong2*>(sp + 2 * COP + 2 * pp);   // dx=+1
                        acc[0][pp]   = ffma2(uL, wA.x, acc[0][pp]);
                        acc[1][pp]   = ffma2(uX, wA.x, acc[1][pp]);
                        acc[2][pp]   = ffma2(uY, wA.x, acc[2][pp]);
                        acc[3][pp]   = ffma2(uZ, wA.x, acc[3][pp]);
                        acc[0][pp+1] = ffma2(uL, wA.y, acc[0][pp+1]);
                        acc[1][pp+1] = ffma2(uX, wA.y, acc[1][pp+1]);
                        acc[2][pp+1] = ffma2(uY, wA.y, acc[2][pp+1]);
                        acc[3][pp+1] = ffma2(uZ, wA.y, acc[3][pp+1]);
                        acc[0][pp]   = ffma2(uX, wB.x, acc[0][pp]);
                        acc[1][pp]   = ffma2(uY, wB.x, acc[1][pp]);
                        acc[2][pp]   = ffma2(uZ, wB.x, acc[2][pp]);
                        acc[3][pp]   = ffma2(uW, wB.x, acc[3][pp]);
                        acc[0][pp+1] = ffma2(uX, wB.y, acc[0][pp+1]);
                        acc[1][pp+1] = ffma2(uY, wB.y, acc[1][pp+1]);
                        acc[2][pp+1] = ffma2(uZ, wB.y, acc[2][pp+1]);
                        acc[3][pp+1] = ffma2(uW, wB.y, acc[3][pp+1]);
                        acc[0][pp]   = ffma2(uY, wC.x, acc[0][pp]);
                        acc[1][pp]   = ffma2(uZ, wC.x, acc[1][pp]);
                        acc[2][pp]   = ffma2(uW, wC.x, acc[2][pp]);
                        acc[3][pp]   = ffma2(uR, wC.x, acc[3][pp]);
                        acc[0][pp+1] = ffma2(uY, wC.y, acc[0][pp+1]);
                        acc[1][pp+1] = ffma2(uZ, wC.y, acc[1][pp+1]);
                        acc[2][pp+1] = ffma2(uW, wC.y, acc[2][pp+1]);
                        acc[3][pp+1] = ffma2(uR, wC.y, acc[3][pp+1]);
                    }
                } else {
#pragma unroll
                    for (int p = 0; p < CP; p++) {
                        ull wA = *reinterpret_cast<const ull*>(sp + 2 * p);
                        ull wB = *reinterpret_cast<const ull*>(sp + COP + 2 * p);
                        ull wC = *reinterpret_cast<const ull*>(sp + 2 * COP + 2 * p);
                        acc[0][p] = ffma2(uL, wA, acc[0][p]);
                        acc[1][p] = ffma2(uX, wA, acc[1][p]);
                        acc[2][p] = ffma2(uY, wA, acc[2][p]);
                        acc[3][p] = ffma2(uZ, wA, acc[3][p]);
                        acc[0][p] = ffma2(uX, wB, acc[0][p]);
                        acc[1][p] = ffma2(uY, wB, acc[1][p]);
                        acc[2][p] = ffma2(uZ, wB, acc[2][p]);
                        acc[3][p] = ffma2(uW, wB, acc[3][p]);
                        acc[0][p] = ffma2(uY, wC, acc[0][p]);
                        acc[1][p] = ffma2(uZ, wC, acc[1][p]);
                        acc[2][p] = ffma2(uW, wC, acc[2][p]);
                        acc[3][p] = ffma2(uR, wC, acc[3][p]);
                    }
                }
            }
        }
    }

    if (NORM) {
        float inv[4];
#pragma unroll
        for (int v = 0; v < 4; v++) {
            float s = 0.f;
#pragma unroll
            for (int p = 0; p < CP; p++) {
                float2 u = f2un(acc[v][p]);
                s += fabsf(u.x) + fabsf(u.y);
            }
            inv[v] = 1.f / fmaxf(s, 1e-12f);
        }
#pragma unroll
        for (int p = 0; p < CP; p++) {
            float2 u0 = f2un(acc[0][p]), u1 = f2un(acc[1][p]);
            float2 u2 = f2un(acc[2][p]), u3 = f2un(acc[3][p]);
            if (2 * p < CO) {
                float4 st; st.x = u0.x * inv[0]; st.y = u1.x * inv[1];
                st.z = u2.x * inv[2]; st.w = u3.x * inv[3];
                *reinterpret_cast<float4*>(out + (2 * p) * VOL + pos) = st;
            }
            if (2 * p + 1 < CO) {
                float4 st; st.x = u0.y * inv[0]; st.y = u1.y * inv[1];
                st.z = u2.y * inv[2]; st.w = u3.y * inv[3];
                *reinterpret_cast<float4*>(out + (2 * p + 1) * VOL + pos) = st;
            }
        }
    } else {
#pragma unroll
        for (int p = 0; p < CP; p++) {
            float2 u0 = f2un(acc[0][p]), u1 = f2un(acc[1][p]);
            float2 u2 = f2un(acc[2][p]), u3 = f2un(acc[3][p]);
            if (RELU) {
                u0.x = fmaxf(u0.x, 0.f); u0.y = fmaxf(u0.y, 0.f);
                u1.x = fmaxf(u1.x, 0.f); u1.y = fmaxf(u1.y, 0.f);
                u2.x = fmaxf(u2.x, 0.f); u2.y = fmaxf(u2.y, 0.f);
                u3.x = fmaxf(u3.x, 0.f); u3.y = fmaxf(u3.y, 0.f);
            }
            if (2 * p < CO) {
                float4 st; st.x = u0.x; st.y = u1.x; st.z = u2.x; st.w = u3.x;
                *reinterpret_cast<float4*>(out + (2 * p) * VOL + pos) = st;
            }
            if (2 * p + 1 < CO) {
                float4 st; st.x = u0.y; st.y = u1.y; st.z = u2.y; st.w = u3.y;
                *reinterpret_cast<float4*>(out + (2 * p + 1) * VOL + pos) = st;
            }
        }
    }
}

// ---------------------------------------------------------------------------
// Adaptive conv: out[c][v] = sum_tap in[c][v + off(tap)] * w[tap][v]
// 4 voxels per thread; loads batched per (dz,dy) in groups of 4 channels to
// maximize memory-level parallelism (front-batched LDGs), then FMA burst.
// ---------------------------------------------------------------------------
template<int C>
__global__ void __launch_bounds__(128) adapt_k(
    const float* __restrict__ in, const float* __restrict__ wt,
    float* __restrict__ out)
{
    constexpr int BC = (C < 4) ? C : 4;   // channel batch size

    int t  = blockIdx.x * 128 + threadIdx.x;   // [0, VOL/4)
    int w0 = (t & 31) << 2;
    int h  = (t >> 5) & 127;
    int d  = t >> 12;
    int pos = (d << 14) + (h << 7) + w0;

    ull accA[C], accB[C];
#pragma unroll
    for (int c = 0; c < C; c++) { accA[c] = 0ull; accB[c] = 0ull; }

    bool wl = (w0 > 0);
    bool wr = (w0 < 124);

#pragma unroll
    for (int dz = -1; dz <= 1; dz++) {
        bool zok = (unsigned)(d + dz) < 128u;
#pragma unroll
        for (int dy = -1; dy <= 1; dy++) {
            bool ok = zok && ((unsigned)(h + dy) < 128u);
            int tap = (dz + 1) * 9 + (dy + 1) * 3;
            const float* wp = wt + tap * VOL + pos;
            ulonglong2 q0 = *reinterpret_cast<const ulonglong2*>(wp);            // dx=-1
            ulonglong2 q1 = *reinterpret_cast<const ulonglong2*>(wp + VOL);      // dx= 0
            ulonglong2 q2 = *reinterpret_cast<const ulonglong2*>(wp + 2 * VOL);  // dx=+1
            int off = dz * PL + dy * NN;
#pragma unroll
            for (int b = 0; b < C; b += BC) {
                float4 cv[BC]; float vl[BC], vr[BC];
                // front-batched loads for this channel group
#pragma unroll
                for (int u = 0; u < BC; u++) {
                    const float* r = in + (b + u) * VOL + pos + off;
                    if (ok) cv[u] = *reinterpret_cast<const float4*>(r);
                    else    { cv[u].x = 0.f; cv[u].y = 0.f; cv[u].z = 0.f; cv[u].w = 0.f; }
                    vl[u] = (ok && wl) ? r[-1] : 0.f;
                    vr[u] = (ok && wr) ? r[4]  : 0.f;
                }
#pragma unroll
                for (int u = 0; u < BC; u++) {
                    int c = b + u;
                    ull pm1  = f2pk(vl[u],   cv[u].x);   // dx=-1, vox (0,1)
                    ull pmid = f2pk(cv[u].y, cv[u].z);   // dx=-1 vox(2,3) & dx=+1 vox(0,1)
                    ull p01  = f2pk(cv[u].x, cv[u].y);   // dx= 0, vox (0,1)
                    ull p23  = f2pk(cv[u].z, cv[u].w);   // dx= 0, vox (2,3)
                    ull pp2  = f2pk(cv[u].w, vr[u]);     // dx=+1, vox (2,3)
                    accA[c] = ffma2(pm1,  q0.x, accA[c]);
                    accB[c] = ffma2(pmid, q0.y, accB[c]);
                    accA[c] = ffma2(p01,  q1.x, accA[c]);
                    accB[c] = ffma2(p23,  q1.y, accB[c]);
                    accA[c] = ffma2(pmid, q2.x, accA[c]);
                    accB[c] = ffma2(pp2,  q2.y, accB[c]);
                }
            }
        }
    }
#pragma unroll
    for (int c = 0; c < C; c++) {
        float2 a = f2un(accA[c]);
        float2 b = f2un(accB[c]);
        float4 st; st.x = a.x; st.y = a.y; st.z = b.x; st.w = b.y;
        *reinterpret_cast<float4*>(out + c * VOL + pos) = st;
    }
}

extern "C" void kernel_launch(void* const* d_in, const int* in_sizes, int n_in,
                              void* d_out, int out_size)
{
    const float* x    = (const float*)d_in[0];
    const float* a1w1 = (const float*)d_in[1];
    const float* a1b1 = (const float*)d_in[2];
    const float* a1w2 = (const float*)d_in[3];
    const float* a2w1 = (const float*)d_in[4];
    const float* a2b1 = (const float*)d_in[5];
    const float* a2w2 = (const float*)d_in[6];
    const float* a3w1 = (const float*)d_in[7];
    const float* a3b1 = (const float*)d_in[8];
    const float* a3w2 = (const float*)d_in[9];
    const float* midw = (const float*)d_in[10];
    const float* midb = (const float*)d_in[11];
    const float* outw = (const float*)d_in[12];
    const float* outb = (const float*)d_in[13];
    float* y = (float*)d_out;

    float *A, *B, *C, *W, *f1, *f2;
    cudaGetSymbolAddress((void**)&A,  g_A);
    cudaGetSymbolAddress((void**)&B,  g_B);
    cudaGetSymbolAddress((void**)&C,  g_C);
    cudaGetSymbolAddress((void**)&W,  g_W);
    cudaGetSymbolAddress((void**)&f1, g_f1);
    cudaGetSymbolAddress((void**)&f2, g_f2);

    dim3 g(VOL / 512);   // 4096 blocks * 128 threads * 4 voxels
    dim3 bl(128);

    // ---- block 1 (weights from x) ----
    conv_k<8,  true,  false, true ><<<g, bl>>>(x, a1w1, a1b1, A);
    conv_k<27, false, true,  false><<<g, bl>>>(A, a1w2, nullptr, W);
    adapt_k<8><<<g, bl>>>(x, W, A);
    adapt_k<8><<<g, bl>>>(A, W, B);
    adapt_k<8><<<g, bl>>>(B, W, A);              // block1 out -> A

    // ---- mid conv ----
    conv_k<8,  false, false, true ><<<g, bl>>>(A, midw, midb, B);   // mid -> B

    // ---- block 2 (weights from mid) ----
    conv_k<8,  true,  false, true ><<<g, bl>>>(B, a2w1, a2b1, A);
    conv_k<27, false, true,  false><<<g, bl>>>(A, a2w2, nullptr, W);
    adapt_k<8><<<g, bl>>>(B, W, A);
    adapt_k<8><<<g, bl>>>(A, W, C);
    adapt_k<8><<<g, bl>>>(C, W, A);              // block2 out (mid2) -> A

    // ---- out conv (8 -> 1) ----
    conv_k<1,  false, false, true ><<<g, bl>>>(A, outw, outb, f1);

    // ---- block 3 (weights from mid2 = A, applied to 1-channel final) ----
    conv_k<8,  true,  false, true ><<<g, bl>>>(A, a3w1, a3b1, B);
    conv_k<27, false, true,  false><<<g, bl>>>(B, a3w2, nullptr, W);
    adapt_k<1><<<g, bl>>>(f1, W, f2);
    adapt_k<1><<<g, bl>>>(f2, W, f1);
    adapt_k<1><<<g, bl>>>(f1, W, y);
}

// round 4
// speedup vs baseline: 1.1659x; 1.0475x over previous
#include <cuda_runtime.h>
#include <cstddef>

#define NN   128
#define PL   16384      // 128*128
#define VOL  2097152    // 128^3

typedef unsigned long long ull;

__device__ float g_A[8 * VOL];
__device__ float g_B[8 * VOL];
__device__ float g_C[8 * VOL];
__device__ float g_W[27 * VOL];
__device__ float g_f1[VOL];
__device__ float g_f2[VOL];

// ---- packed f32x2 helpers -------------------------------------------------
__device__ __forceinline__ ull f2pk(float lo, float hi) {
    ull r; asm("mov.b64 %0, {%1, %2};" : "=l"(r) : "f"(lo), "f"(hi)); return r;
}
__device__ __forceinline__ float2 f2un(ull v) {
    float2 r; asm("mov.b64 {%0, %1}, %2;" : "=f"(r.x), "=f"(r.y) : "l"(v)); return r;
}
__device__ __forceinline__ ull ffma2(ull a, ull b, ull c) {
    ull d; asm("fma.rn.f32x2 %0, %1, %2, %3;" : "=l"(d) : "l"(a), "l"(b), "l"(c)); return d;
}

// ---------------------------------------------------------------------------
// 3x3x3 conv, C_in=8, C_out=CO. 4 voxels per thread along w.
// Per dz-slab: all 3 input rows (9 LDG) are front-batched (MLP=9), then the
// slab's FFMA2 burst (up to 504 inst) runs with loads already in flight.
// Weights staged co-major in shared, read as LDS.128 quads.
// ---------------------------------------------------------------------------
template<int CO, bool RELU, bool NORM, bool HB>
__global__ void __launch_bounds__(128) conv_k(
    const float* __restrict__ in, const float* __restrict__ wgt,
    const float* __restrict__ bias, float* __restrict__ out)
{
    constexpr int COP = (CO + 1) & ~1;   // 2, 8, 28
    constexpr int CP  = COP / 2;
    __shared__ __align__(16) float sw[8 * 27 * COP];

    for (int i = threadIdx.x; i < 8 * 27 * COP; i += 128) {
        int co   = i % COP;
        int rest = i / COP;          // ci*27 + tap
        int ci   = rest / 27;
        int tap  = rest % 27;
        sw[i] = (co < CO) ? wgt[(co * 8 + ci) * 27 + tap] : 0.f;
    }
    __syncthreads();

    int t  = blockIdx.x * 128 + threadIdx.x;   // [0, VOL/4)
    int w0 = (t & 31) << 2;
    int h  = (t >> 5) & 127;
    int d  = t >> 12;
    int pos = (d << 14) + (h << 7) + w0;

    ull acc[4][CP];
#pragma unroll
    for (int p = 0; p < CP; p++) {
        float blo = 0.f, bhi = 0.f;
        if (HB) {
            if (2 * p     < CO) blo = bias[2 * p];
            if (2 * p + 1 < CO) bhi = bias[2 * p + 1];
        }
        ull b = f2pk(blo, bhi);
#pragma unroll
        for (int v = 0; v < 4; v++) acc[v][p] = b;
    }

    bool wl = (w0 > 0);
    bool wr = (w0 < 124);

#pragma unroll 1
    for (int ci = 0; ci < 8; ci++) {
        const float* cb  = in + ci * VOL + pos;
        const float* swc = sw + ci * 27 * COP;
#pragma unroll
        for (int dz = -1; dz <= 1; dz++) {
            bool zok = (unsigned)(d + dz) < 128u;
            // ---- front-batched loads for the whole dz slab (3 rows) ----
            float4 cv[3]; float vl[3], vr[3];
#pragma unroll
            for (int iy = 0; iy < 3; iy++) {
                bool ok = zok && ((unsigned)(h + iy - 1) < 128u);
                const float* r = cb + dz * PL + (iy - 1) * NN;
                if (ok) cv[iy] = *reinterpret_cast<const float4*>(r);
                else    { cv[iy].x = 0.f; cv[iy].y = 0.f; cv[iy].z = 0.f; cv[iy].w = 0.f; }
                vl[iy] = (ok && wl) ? r[-1] : 0.f;
                vr[iy] = (ok && wr) ? r[4]  : 0.f;
            }
            // ---- FMA burst over the 3 rows ----
#pragma unroll
            for (int iy = 0; iy < 3; iy++) {
                ull uL = f2pk(vl[iy],   vl[iy]);
                ull uX = f2pk(cv[iy].x, cv[iy].x);
                ull uY = f2pk(cv[iy].y, cv[iy].y);
                ull uZ = f2pk(cv[iy].z, cv[iy].z);
                ull uW = f2pk(cv[iy].w, cv[iy].w);
                ull uR = f2pk(vr[iy],   vr[iy]);
                const float* sp = swc + ((dz + 1) * 9 + iy * 3) * COP;
                if constexpr (CP % 2 == 0) {
#pragma unroll
                    for (int pp = 0; pp < CP; pp += 2) {
                        ulonglong2 wA = *reinterpret_cast<const ulonglong2*>(sp + 2 * pp);             // dx=-1
                        ulonglong2 wB = *reinterpret_cast<const ulonglong2*>(sp + COP + 2 * pp);       // dx= 0
                        ulonglong2 wC = *reinterpret_cast<const ulonglong2*>(sp + 2 * COP + 2 * pp);   // dx=+1
                        acc[0][pp]   = ffma2(uL, wA.x, acc[0][pp]);
                        acc[1][pp]   = ffma2(uX, wA.x, acc[1][pp]);
                        acc[2][pp]   = ffma2(uY, wA.x, acc[2][pp]);
                        acc[3][pp]   = ffma2(uZ, wA.x, acc[3][pp]);
                        acc[0][pp+1] = ffma2(uL, wA.y, acc[0][pp+1]);
                        acc[1][pp+1] = ffma2(uX, wA.y, acc[1][pp+1]);
                        acc[2][pp+1] = ffma2(uY, wA.y, acc[2][pp+1]);
                        acc[3][pp+1] = ffma2(uZ, wA.y, acc[3][pp+1]);
                        acc[0][pp]   = ffma2(uX, wB.x, acc[0][pp]);
                        acc[1][pp]   = ffma2(uY, wB.x, acc[1][pp]);
                        acc[2][pp]   = ffma2(uZ, wB.x, acc[2][pp]);
                        acc[3][pp]   = ffma2(uW, wB.x, acc[3][pp]);
                        acc[0][pp+1] = ffma2(uX, wB.y, acc[0][pp+1]);
                        acc[1][pp+1] = ffma2(uY, wB.y, acc[1][pp+1]);
                        acc[2][pp+1] = ffma2(uZ, wB.y, acc[2][pp+1]);
                        acc[3][pp+1] = ffma2(uW, wB.y, acc[3][pp+1]);
                        acc[0][pp]   = ffma2(uY, wC.x, acc[0][pp]);
                        acc[1][pp]   = ffma2(uZ, wC.x, acc[1][pp]);
                        acc[2][pp]   = ffma2(uW, wC.x, acc[2][pp]);
                        acc[3][pp]   = ffma2(uR, wC.x, acc[3][pp]);
                        acc[0][pp+1] = ffma2(uY, wC.y, acc[0][pp+1]);
                        acc[1][pp+1] = ffma2(uZ, wC.y, acc[1][pp+1]);
                        acc[2][pp+1] = ffma2(uW, wC.y, acc[2][pp+1]);
                        acc[3][pp+1] = ffma2(uR, wC.y, acc[3][pp+1]);
                    }
                } else {
#pragma unroll
                    for (int p = 0; p < CP; p++) {
                        ull wA = *reinterpret_cast<const ull*>(sp + 2 * p);
                        ull wB = *reinterpret_cast<const ull*>(sp + COP + 2 * p);
                        ull wC = *reinterpret_cast<const ull*>(sp + 2 * COP + 2 * p);
                        acc[0][p] = ffma2(uL, wA, acc[0][p]);
                        acc[1][p] = ffma2(uX, wA, acc[1][p]);
                        acc[2][p] = ffma2(uY, wA, acc[2][p]);
                        acc[3][p] = ffma2(uZ, wA, acc[3][p]);
                        acc[0][p] = ffma2(uX, wB, acc[0][p]);
                        acc[1][p] = ffma2(uY, wB, acc[1][p]);
                        acc[2][p] = ffma2(uZ, wB, acc[2][p]);
                        acc[3][p] = ffma2(uW, wB, acc[3][p]);
                        acc[0][p] = ffma2(uY, wC, acc[0][p]);
                        acc[1][p] = ffma2(uZ, wC, acc[1][p]);
                        acc[2][p] = ffma2(uW, wC, acc[2][p]);
                        acc[3][p] = ffma2(uR, wC, acc[3][p]);
                    }
                }
            }
        }
    }

    if (NORM) {
        float inv[4];
#pragma unroll
        for (int v = 0; v < 4; v++) {
            float s = 0.f;
#pragma unroll
            for (int p = 0; p < CP; p++) {
                float2 u = f2un(acc[v][p]);
                s += fabsf(u.x) + fabsf(u.y);
            }
            inv[v] = 1.f / fmaxf(s, 1e-12f);
        }
#pragma unroll
        for (int p = 0; p < CP; p++) {
            float2 u0 = f2un(acc[0][p]), u1 = f2un(acc[1][p]);
            float2 u2 = f2un(acc[2][p]), u3 = f2un(acc[3][p]);
            if (2 * p < CO) {
                float4 st; st.x = u0.x * inv[0]; st.y = u1.x * inv[1];
                st.z = u2.x * inv[2]; st.w = u3.x * inv[3];
                *reinterpret_cast<float4*>(out + (2 * p) * VOL + pos) = st;
            }
            if (2 * p + 1 < CO) {
                float4 st; st.x = u0.y * inv[0]; st.y = u1.y * inv[1];
                st.z = u2.y * inv[2]; st.w = u3.y * inv[3];
                *reinterpret_cast<float4*>(out + (2 * p + 1) * VOL + pos) = st;
            }
        }
    } else {
#pragma unroll
        for (int p = 0; p < CP; p++) {
            float2 u0 = f2un(acc[0][p]), u1 = f2un(acc[1][p]);
            float2 u2 = f2un(acc[2][p]), u3 = f2un(acc[3][p]);
            if (RELU) {
                u0.x = fmaxf(u0.x, 0.f); u0.y = fmaxf(u0.y, 0.f);
                u1.x = fmaxf(u1.x, 0.f); u1.y = fmaxf(u1.y, 0.f);
                u2.x = fmaxf(u2.x, 0.f); u2.y = fmaxf(u2.y, 0.f);
                u3.x = fmaxf(u3.x, 0.f); u3.y = fmaxf(u3.y, 0.f);
            }
            if (2 * p < CO) {
                float4 st; st.x = u0.x; st.y = u1.x; st.z = u2.x; st.w = u3.x;
                *reinterpret_cast<float4*>(out + (2 * p) * VOL + pos) = st;
            }
            if (2 * p + 1 < CO) {
                float4 st; st.x = u0.y; st.y = u1.y; st.z = u2.y; st.w = u3.y;
                *reinterpret_cast<float4*>(out + (2 * p + 1) * VOL + pos) = st;
            }
        }
    }
}

// ---------------------------------------------------------------------------
// Adaptive conv: out[c][v] = sum_tap in[c][v + off(tap)] * w[tap][v]
// 4 voxels per thread; loads batched per (dz,dy) in groups of 4 channels.
// ---------------------------------------------------------------------------
template<int C>
__global__ void __launch_bounds__(128) adapt_k(
    const float* __restrict__ in, const float* __restrict__ wt,
    float* __restrict__ out)
{
    constexpr int BC = (C < 4) ? C : 4;   // channel batch size

    int t  = blockIdx.x * 128 + threadIdx.x;   // [0, VOL/4)
    int w0 = (t & 31) << 2;
    int h  = (t >> 5) & 127;
    int d  = t >> 12;
    int pos = (d << 14) + (h << 7) + w0;

    ull accA[C], accB[C];
#pragma unroll
    for (int c = 0; c < C; c++) { accA[c] = 0ull; accB[c] = 0ull; }

    bool wl = (w0 > 0);
    bool wr = (w0 < 124);

#pragma unroll
    for (int dz = -1; dz <= 1; dz++) {
        bool zok = (unsigned)(d + dz) < 128u;
#pragma unroll
        for (int dy = -1; dy <= 1; dy++) {
            bool ok = zok && ((unsigned)(h + dy) < 128u);
            int tap = (dz + 1) * 9 + (dy + 1) * 3;
            const float* wp = wt + tap * VOL + pos;
            ulonglong2 q0 = *reinterpret_cast<const ulonglong2*>(wp);            // dx=-1
            ulonglong2 q1 = *reinterpret_cast<const ulonglong2*>(wp + VOL);      // dx= 0
            ulonglong2 q2 = *reinterpret_cast<const ulonglong2*>(wp + 2 * VOL);  // dx=+1
            int off = dz * PL + dy * NN;
#pragma unroll
            for (int b = 0; b < C; b += BC) {
                float4 cv[BC]; float vl[BC], vr[BC];
#pragma unroll
                for (int u = 0; u < BC; u++) {
                    const float* r = in + (b + u) * VOL + pos + off;
                    if (ok) cv[u] = *reinterpret_cast<const float4*>(r);
                    else    { cv[u].x = 0.f; cv[u].y = 0.f; cv[u].z = 0.f; cv[u].w = 0.f; }
                    vl[u] = (ok && wl) ? r[-1] : 0.f;
                    vr[u] = (ok && wr) ? r[4]  : 0.f;
                }
#pragma unroll
                for (int u = 0; u < BC; u++) {
                    int c = b + u;
                    ull pm1  = f2pk(vl[u],   cv[u].x);
                    ull pmid = f2pk(cv[u].y, cv[u].z);
                    ull p01  = f2pk(cv[u].x, cv[u].y);
                    ull p23  = f2pk(cv[u].z, cv[u].w);
                    ull pp2  = f2pk(cv[u].w, vr[u]);
                    accA[c] = ffma2(pm1,  q0.x, accA[c]);
                    accB[c] = ffma2(pmid, q0.y, accB[c]);
                    accA[c] = ffma2(p01,  q1.x, accA[c]);
                    accB[c] = ffma2(p23,  q1.y, accB[c]);
                    accA[c] = ffma2(pmid, q2.x, accA[c]);
                    accB[c] = ffma2(pp2,  q2.y, accB[c]);
                }
            }
        }
    }
#pragma unroll
    for (int c = 0; c < C; c++) {
        float2 a = f2un(accA[c]);
        float2 b = f2un(accB[c]);
        float4 st; st.x = a.x; st.y = a.y; st.z = b.x; st.w = b.y;
        *reinterpret_cast<float4*>(out + c * VOL + pos) = st;
    }
}

extern "C" void kernel_launch(void* const* d_in, const int* in_sizes, int n_in,
                              void* d_out, int out_size)
{
    const float* x    = (const float*)d_in[0];
    const float* a1w1 = (const float*)d_in[1];
    const float* a1b1 = (const float*)d_in[2];
    const float* a1w2 = (const float*)d_in[3];
    const float* a2w1 = (const float*)d_in[4];
    const float* a2b1 = (const float*)d_in[5];
    const float* a2w2 = (const float*)d_in[6];
    const float* a3w1 = (const float*)d_in[7];
    const float* a3b1 = (const float*)d_in[8];
    const float* a3w2 = (const float*)d_in[9];
    const float* midw = (const float*)d_in[10];
    const float* midb = (const float*)d_in[11];
    const float* outw = (const float*)d_in[12];
    const float* outb = (const float*)d_in[13];
    float* y = (float*)d_out;

    float *A, *B, *C, *W, *f1, *f2;
    cudaGetSymbolAddress((void**)&A,  g_A);
    cudaGetSymbolAddress((void**)&B,  g_B);
    cudaGetSymbolAddress((void**)&C,  g_C);
    cudaGetSymbolAddress((void**)&W,  g_W);
    cudaGetSymbolAddress((void**)&f1, g_f1);
    cudaGetSymbolAddress((void**)&f2, g_f2);

    dim3 g(VOL / 512);   // 4096 blocks * 128 threads * 4 voxels
    dim3 bl(128);

    // ---- block 1 (weights from x) ----
    conv_k<8,  true,  false, true ><<<g, bl>>>(x, a1w1, a1b1, A);
    conv_k<27, false, true,  false><<<g, bl>>>(A, a1w2, nullptr, W);
    adapt_k<8><<<g, bl>>>(x, W, A);
    adapt_k<8><<<g, bl>>>(A, W, B);
    adapt_k<8><<<g, bl>>>(B, W, A);              // block1 out -> A

    // ---- mid conv ----
    conv_k<8,  false, false, true ><<<g, bl>>>(A, midw, midb, B);   // mid -> B

    // ---- block 2 (weights from mid) ----
    conv_k<8,  true,  false, true ><<<g, bl>>>(B, a2w1, a2b1, A);
    conv_k<27, false, true,  false><<<g, bl>>>(A, a2w2, nullptr, W);
    adapt_k<8><<<g, bl>>>(B, W, A);
    adapt_k<8><<<g, bl>>>(A, W, C);
    adapt_k<8><<<g, bl>>>(C, W, A);              // block2 out (mid2) -> A

    // ---- out conv (8 -> 1) ----
    conv_k<1,  false, false, true ><<<g, bl>>>(A, outw, outb, f1);

    // ---- block 3 (weights from mid2 = A, applied to 1-channel final) ----
    conv_k<8,  true,  false, true ><<<g, bl>>>(A, a3w1, a3b1, B);
    conv_k<27, false, true,  false><<<g, bl>>>(B, a3w2, nullptr, W);
    adapt_k<1><<<g, bl>>>(f1, W, f2);
    adapt_k<1><<<g, bl>>>(f2, W, f1);
    adapt_k<1><<<g, bl>>>(f1, W, y);
}

// round 5
// speedup vs baseline: 1.1857x; 1.0170x over previous
#include <cuda_runtime.h>
#include <cstddef>

#define NN   128
#define PL   16384      // 128*128
#define VOL  2097152    // 128^3

typedef unsigned long long ull;

__device__ float g_A[8 * VOL];
__device__ float g_B[8 * VOL];
__device__ float g_C[8 * VOL];
__device__ float g_W[27 * VOL];
__device__ float g_f1[VOL];
__device__ float g_f2[VOL];

// ---- packed f32x2 helpers -------------------------------------------------
__device__ __forceinline__ ull f2pk(float lo, float hi) {
    ull r; asm("mov.b64 %0, {%1, %2};" : "=l"(r) : "f"(lo), "f"(hi)); return r;
}
__device__ __forceinline__ float2 f2un(ull v) {
    float2 r; asm("mov.b64 {%0, %1}, %2;" : "=f"(r.x), "=f"(r.y) : "l"(v)); return r;
}
__device__ __forceinline__ ull ffma2(ull a, ull b, ull c) {
    ull d; asm("fma.rn.f32x2 %0, %1, %2, %3;" : "=l"(d) : "l"(a), "l"(b), "l"(c)); return d;
}

// ---------------------------------------------------------------------------
// 3x3x3 conv, C_in=8, C_out=CO, V voxels per thread along w (2 or 4).
// V chosen per CO so accumulator register pressure keeps occupancy high:
//   CO=27 -> V=2 (56 acc regs), CO=8/1 -> V=4.
// Per dz-slab all 3 input rows are front-batched; weights staged co-major in
// shared and read as LDS.128 quads (CP even) or LDS.64 (CP odd).
// ---------------------------------------------------------------------------
template<int CO, int V, bool RELU, bool NORM, bool HB>
__global__ void __launch_bounds__(128) conv_k(
    const float* __restrict__ in, const float* __restrict__ wgt,
    const float* __restrict__ bias, float* __restrict__ out)
{
    constexpr int COP   = (CO + 1) & ~1;   // 2, 8, 28
    constexpr int CP    = COP / 2;
    constexpr int LANES = 128 / V;         // threads per w-row
    __shared__ __align__(16) float sw[8 * 27 * COP];

    for (int i = threadIdx.x; i < 8 * 27 * COP; i += 128) {
        int co   = i % COP;
        int rest = i / COP;          // ci*27 + tap
        int ci   = rest / 27;
        int tap  = rest % 27;
        sw[i] = (co < CO) ? wgt[(co * 8 + ci) * 27 + tap] : 0.f;
    }
    __syncthreads();

    int t  = blockIdx.x * 128 + threadIdx.x;   // [0, VOL/V)
    int wi = t % LANES;
    int w0 = wi * V;
    int rest = t / LANES;
    int h  = rest & 127;
    int d  = rest >> 7;
    int pos = (d << 14) + (h << 7) + w0;

    ull acc[V][CP];
#pragma unroll
    for (int p = 0; p < CP; p++) {
        float blo = 0.f, bhi = 0.f;
        if (HB) {
            if (2 * p     < CO) blo = bias[2 * p];
            if (2 * p + 1 < CO) bhi = bias[2 * p + 1];
        }
        ull b = f2pk(blo, bhi);
#pragma unroll
        for (int v = 0; v < V; v++) acc[v][p] = b;
    }

    bool wl = (w0 > 0);
    bool wr = (w0 < 128 - V);

#pragma unroll 1
    for (int ci = 0; ci < 8; ci++) {
        const float* cb  = in + ci * VOL + pos;
        const float* swc = sw + ci * 27 * COP;
#pragma unroll
        for (int dz = -1; dz <= 1; dz++) {
            bool zok = (unsigned)(d + dz) < 128u;
            // ---- front-batched loads for the whole dz slab (3 rows) ----
            float val[3][V + 2];
#pragma unroll
            for (int iy = 0; iy < 3; iy++) {
                bool ok = zok && ((unsigned)(h + iy - 1) < 128u);
                const float* r = cb + dz * PL + (iy - 1) * NN;
                if constexpr (V == 4) {
                    float4 cv;
                    if (ok) cv = *reinterpret_cast<const float4*>(r);
                    else    { cv.x = 0.f; cv.y = 0.f; cv.z = 0.f; cv.w = 0.f; }
                    val[iy][1] = cv.x; val[iy][2] = cv.y;
                    val[iy][3] = cv.z; val[iy][4] = cv.w;
                } else {
                    float2 cv;
                    if (ok) cv = *reinterpret_cast<const float2*>(r);
                    else    { cv.x = 0.f; cv.y = 0.f; }
                    val[iy][1] = cv.x; val[iy][2] = cv.y;
                }
                val[iy][0]     = (ok && wl) ? r[-1] : 0.f;
                val[iy][V + 1] = (ok && wr) ? r[V]  : 0.f;
            }
            // ---- FMA burst over the 3 rows ----
#pragma unroll
            for (int iy = 0; iy < 3; iy++) {
                ull u[V + 2];
#pragma unroll
                for (int i = 0; i < V + 2; i++) u[i] = f2pk(val[iy][i], val[iy][i]);
                const float* sp = swc + ((dz + 1) * 9 + iy * 3) * COP;
                if constexpr (CP % 2 == 0) {
#pragma unroll
                    for (int pp = 0; pp < CP; pp += 2) {
                        ulonglong2 wA = *reinterpret_cast<const ulonglong2*>(sp + 2 * pp);             // dx=-1
                        ulonglong2 wB = *reinterpret_cast<const ulonglong2*>(sp + COP + 2 * pp);       // dx= 0
                        ulonglong2 wC = *reinterpret_cast<const ulonglong2*>(sp + 2 * COP + 2 * pp);   // dx=+1
#pragma unroll
                        for (int v = 0; v < V; v++) {
                            acc[v][pp]   = ffma2(u[v],     wA.x, acc[v][pp]);
                            acc[v][pp+1] = ffma2(u[v],     wA.y, acc[v][pp+1]);
                            acc[v][pp]   = ffma2(u[v + 1], wB.x, acc[v][pp]);
                            acc[v][pp+1] = ffma2(u[v + 1], wB.y, acc[v][pp+1]);
                            acc[v][pp]   = ffma2(u[v + 2], wC.x, acc[v][pp]);
                            acc[v][pp+1] = ffma2(u[v + 2], wC.y, acc[v][pp+1]);
                        }
                    }
                } else {
#pragma unroll
                    for (int p = 0; p < CP; p++) {
                        ull wA = *reinterpret_cast<const ull*>(sp + 2 * p);
                        ull wB = *reinterpret_cast<const ull*>(sp + COP + 2 * p);
                        ull wC = *reinterpret_cast<const ull*>(sp + 2 * COP + 2 * p);
#pragma unroll
                        for (int v = 0; v < V; v++) {
                            acc[v][p] = ffma2(u[v],     wA, acc[v][p]);
                            acc[v][p] = ffma2(u[v + 1], wB, acc[v][p]);
                            acc[v][p] = ffma2(u[v + 2], wC, acc[v][p]);
                        }
                    }
                }
            }
        }
    }

    // ---- epilogue ----
    float res[V][COP];
#pragma unroll
    for (int p = 0; p < CP; p++)
#pragma unroll
        for (int v = 0; v < V; v++) {
            float2 uu = f2un(acc[v][p]);
            res[v][2 * p] = uu.x; res[v][2 * p + 1] = uu.y;
        }

    if (NORM) {
#pragma unroll
        for (int v = 0; v < V; v++) {
            float s = 0.f;
#pragma unroll
            for (int c = 0; c < COP; c++) s += fabsf(res[v][c]);
            float inv = 1.f / fmaxf(s, 1e-12f);
#pragma unroll
            for (int c = 0; c < COP; c++) res[v][c] *= inv;
        }
    } else if (RELU) {
#pragma unroll
        for (int v = 0; v < V; v++)
#pragma unroll
            for (int c = 0; c < COP; c++) res[v][c] = fmaxf(res[v][c], 0.f);
    }

#pragma unroll
    for (int c = 0; c < CO; c++) {
        if constexpr (V == 4) {
            float4 st; st.x = res[0][c]; st.y = res[1][c]; st.z = res[2][c]; st.w = res[3][c];
            *reinterpret_cast<float4*>(out + c * VOL + pos) = st;
        } else {
            float2 st; st.x = res[0][c]; st.y = res[1][c];
            *reinterpret_cast<float2*>(out + c * VOL + pos) = st;
        }
    }
}

// ---------------------------------------------------------------------------
// Adaptive conv: out[c][v] = sum_tap in[c][v + off(tap)] * w[tap][v]
// 4 voxels per thread; loads batched per (dz,dy) in groups of 4 channels.
// ---------------------------------------------------------------------------
template<int C>
__global__ void __launch_bounds__(128) adapt_k(
    const float* __restrict__ in, const float* __restrict__ wt,
    float* __restrict__ out)
{
    constexpr int BC = (C < 4) ? C : 4;   // channel batch size

    int t  = blockIdx.x * 128 + threadIdx.x;   // [0, VOL/4)
    int w0 = (t & 31) << 2;
    int h  = (t >> 5) & 127;
    int d  = t >> 12;
    int pos = (d << 14) + (h << 7) + w0;

    ull accA[C], accB[C];
#pragma unroll
    for (int c = 0; c < C; c++) { accA[c] = 0ull; accB[c] = 0ull; }

    bool wl = (w0 > 0);
    bool wr = (w0 < 124);

#pragma unroll
    for (int dz = -1; dz <= 1; dz++) {
        bool zok = (unsigned)(d + dz) < 128u;
#pragma unroll
        for (int dy = -1; dy <= 1; dy++) {
            bool ok = zok && ((unsigned)(h + dy) < 128u);
            int tap = (dz + 1) * 9 + (dy + 1) * 3;
            const float* wp = wt + tap * VOL + pos;
            ulonglong2 q0 = *reinterpret_cast<const ulonglong2*>(wp);            // dx=-1
            ulonglong2 q1 = *reinterpret_cast<const ulonglong2*>(wp + VOL);      // dx= 0
            ulonglong2 q2 = *reinterpret_cast<const ulonglong2*>(wp + 2 * VOL);  // dx=+1
            int off = dz * PL + dy * NN;
#pragma unroll
            for (int b = 0; b < C; b += BC) {
                float4 cv[BC]; float vl[BC], vr[BC];
#pragma unroll
                for (int u = 0; u < BC; u++) {
                    const float* r = in + (b + u) * VOL + pos + off;
                    if (ok) cv[u] = *reinterpret_cast<const float4*>(r);
                    else    { cv[u].x = 0.f; cv[u].y = 0.f; cv[u].z = 0.f; cv[u].w = 0.f; }
                    vl[u] = (ok && wl) ? r[-1] : 0.f;
                    vr[u] = (ok && wr) ? r[4]  : 0.f;
                }
#pragma unroll
                for (int u = 0; u < BC; u++) {
                    int c = b + u;
                    ull pm1  = f2pk(vl[u],   cv[u].x);
                    ull pmid = f2pk(cv[u].y, cv[u].z);
                    ull p01  = f2pk(cv[u].x, cv[u].y);
                    ull p23  = f2pk(cv[u].z, cv[u].w);
                    ull pp2  = f2pk(cv[u].w, vr[u]);
                    accA[c] = ffma2(pm1,  q0.x, accA[c]);
                    accB[c] = ffma2(pmid, q0.y, accB[c]);
                    accA[c] = ffma2(p01,  q1.x, accA[c]);
                    accB[c] = ffma2(p23,  q1.y, accB[c]);
                    accA[c] = ffma2(pmid, q2.x, accA[c]);
                    accB[c] = ffma2(pp2,  q2.y, accB[c]);
                }
            }
        }
    }
#pragma unroll
    for (int c = 0; c < C; c++) {
        float2 a = f2un(accA[c]);
        float2 b = f2un(accB[c]);
        float4 st; st.x = a.x; st.y = a.y; st.z = b.x; st.w = b.y;
        *reinterpret_cast<float4*>(out + c * VOL + pos) = st;
    }
}

extern "C" void kernel_launch(void* const* d_in, const int* in_sizes, int n_in,
                              void* d_out, int out_size)
{
    const float* x    = (const float*)d_in[0];
    const float* a1w1 = (const float*)d_in[1];
    const float* a1b1 = (const float*)d_in[2];
    const float* a1w2 = (const float*)d_in[3];
    const float* a2w1 = (const float*)d_in[4];
    const float* a2b1 = (const float*)d_in[5];
    const float* a2w2 = (const float*)d_in[6];
    const float* a3w1 = (const float*)d_in[7];
    const float* a3b1 = (const float*)d_in[8];
    const float* a3w2 = (const float*)d_in[9];
    const float* midw = (const float*)d_in[10];
    const float* midb = (const float*)d_in[11];
    const float* outw = (const float*)d_in[12];
    const float* outb = (const float*)d_in[13];
    float* y = (float*)d_out;

    float *A, *B, *C, *W, *f1, *f2;
    cudaGetSymbolAddress((void**)&A,  g_A);
    cudaGetSymbolAddress((void**)&B,  g_B);
    cudaGetSymbolAddress((void**)&C,  g_C);
    cudaGetSymbolAddress((void**)&W,  g_W);
    cudaGetSymbolAddress((void**)&f1, g_f1);
    cudaGetSymbolAddress((void**)&f2, g_f2);

    dim3 bl(128);
    dim3 g4(VOL / 512);   // V=4 kernels
    dim3 g2(VOL / 256);   // V=2 kernels (conv27)

    // ---- block 1 (weights from x) ----
    conv_k<8,  4, true,  false, true ><<<g4, bl>>>(x, a1w1, a1b1, A);
    conv_k<27, 2, false, true,  false><<<g2, bl>>>(A, a1w2, nullptr, W);
    adapt_k<8><<<g4, bl>>>(x, W, A);
    adapt_k<8><<<g4, bl>>>(A, W, B);
    adapt_k<8><<<g4, bl>>>(B, W, A);              // block1 out -> A

    // ---- mid conv ----
    conv_k<8,  4, false, false, true ><<<g4, bl>>>(A, midw, midb, B);   // mid -> B

    // ---- block 2 (weights from mid) ----
    conv_k<8,  4, true,  false, true ><<<g4, bl>>>(B, a2w1, a2b1, A);
    conv_k<27, 2, false, true,  false><<<g2, bl>>>(A, a2w2, nullptr, W);
    adapt_k<8><<<g4, bl>>>(B, W, A);
    adapt_k<8><<<g4, bl>>>(A, W, C);
    adapt_k<8><<<g4, bl>>>(C, W, A);              // block2 out (mid2) -> A

    // ---- out conv (8 -> 1) ----
    conv_k<1,  4, false, false, true ><<<g4, bl>>>(A, outw, outb, f1);

    // ---- block 3 (weights from mid2 = A, applied to 1-channel final) ----
    conv_k<8,  4, true,  false, true ><<<g4, bl>>>(A, a3w1, a3b1, B);
    conv_k<27, 2, false, true,  false><<<g2, bl>>>(B, a3w2, nullptr, W);
    adapt_k<1><<<g4, bl>>>(f1, W, f2);
    adapt_k<1><<<g4, bl>>>(f2, W, f1);
    adapt_k<1><<<g4, bl>>>(f1, W, y);
}